// round 2
// baseline (speedup 1.0000x reference)
#include <cuda_runtime.h>
#include <math.h>

#define B_DIM 128
#define N_DIM 1024
#define H_DIM 128

// Scratch for the correlation output (allocation-free rule: device global).
__device__ float g_c[B_DIM * N_DIM];

__device__ __forceinline__ float celu1(float v) {
    return v > 0.f ? v : expm1f(v);
}

// Kernel 1: circular autocorrelation per batch.
// c[b,p] = (1/N) * sum_q sum_d x[b,q,d] * x[b,(p+q)%N,d]
// Symmetry c[p] = c[(N-p)%N] -> compute p = 0..511 (+512 special), mirror the rest.
// One CTA per batch, 128 threads, each thread owns 4 consecutive p values.
// SMEM holds x[b] in SoA, duplicated 2x to kill the modulo.
__global__ __launch_bounds__(128) void corr_kernel(const float* __restrict__ x) {
    __shared__ __align__(16) float xs[3][2 * N_DIM];

    const int b   = blockIdx.x;
    const int tid = threadIdx.x;
    const float* xb = x + (size_t)b * N_DIM * 3;

    // Load (N,3) -> SoA, duplicated.
    for (int i = tid; i < N_DIM * 3; i += 128) {
        float v = xb[i];
        int q = i / 3;
        int d = i - 3 * q;
        xs[d][q]         = v;
        xs[d][q + N_DIM] = v;
    }
    __syncthreads();

    const int p0 = tid * 4;   // p0 multiple of 4 -> float4-aligned window loads

    float acc[3][4];
#pragma unroll
    for (int d = 0; d < 3; d++)
#pragma unroll
        for (int j = 0; j < 4; j++) acc[d][j] = 0.f;

    // Sliding register window: win[d][0..7] = xs[d][q+p0 .. q+p0+7]
    float win[3][8];
#pragma unroll
    for (int d = 0; d < 3; d++) {
        float4 t = *(const float4*)&xs[d][p0];
        win[d][0] = t.x; win[d][1] = t.y; win[d][2] = t.z; win[d][3] = t.w;
    }

#pragma unroll 2
    for (int q = 0; q < N_DIM; q += 4) {
        float bb[3][4];
#pragma unroll
        for (int d = 0; d < 3; d++) {
            float4 t = *(const float4*)&xs[d][q];            // broadcast across warp
            bb[d][0] = t.x; bb[d][1] = t.y; bb[d][2] = t.z; bb[d][3] = t.w;
            float4 u = *(const float4*)&xs[d][q + p0 + 4];    // dense, conflict-free
            win[d][4] = u.x; win[d][5] = u.y; win[d][6] = u.z; win[d][7] = u.w;
        }
#pragma unroll
        for (int d = 0; d < 3; d++)
#pragma unroll
            for (int s = 0; s < 4; s++)
#pragma unroll
                for (int j = 0; j < 4; j++)
                    acc[d][j] = fmaf(bb[d][s], win[d][s + j], acc[d][j]);
        // shift window
#pragma unroll
        for (int d = 0; d < 3; d++)
#pragma unroll
            for (int m = 0; m < 4; m++) win[d][m] = win[d][m + 4];
    }

    const float inv = 1.0f / (float)N_DIM;
    float* cb = g_c + b * N_DIM;
#pragma unroll
    for (int j = 0; j < 4; j++) {
        int p = p0 + j;                       // 0..511
        float v = (acc[0][j] + acc[1][j] + acc[2][j]) * inv;
        cb[p] = v;
        if (p > 0) cb[N_DIM - p] = v;         // mirror: 513..1023
    }

    // p = 512 (self-mirror), warp 0 only.
    if (tid < 32) {
        float s = 0.f;
        for (int q = tid; q < N_DIM; q += 32) {
            s = fmaf(xs[0][q], xs[0][q + 512], s);
            s = fmaf(xs[1][q], xs[1][q + 512], s);
            s = fmaf(xs[2][q], xs[2][q + 512], s);
        }
#pragma unroll
        for (int off = 16; off; off >>= 1)
            s += __shfl_xor_sync(0xffffffffu, s, off);
        if (tid == 0) cb[512] = s * inv;
    }
}

// Kernel 2: the MLP. 2 batch rows per CTA (halves W1 L2 traffic), 128 threads.
// thread j owns output column j of h1/h2; W1/W2 column reads are coalesced.
__global__ __launch_bounds__(128) void mlp_kernel(
    const float* __restrict__ W1, const float* __restrict__ b1,
    const float* __restrict__ W2, const float* __restrict__ b2,
    const float* __restrict__ W3, const float* __restrict__ b3,
    float* __restrict__ y)
{
    __shared__ float cs[2][N_DIM];
    __shared__ float h1s[2][H_DIM];
    __shared__ float red[2][4];

    const int b0  = blockIdx.x * 2;
    const int tid = threadIdx.x;   // 0..127
    const int j   = tid;

    for (int i = tid; i < 2 * N_DIM; i += 128)
        cs[i >> 10][i & (N_DIM - 1)] = g_c[b0 * N_DIM + i];
    __syncthreads();

    float a0 = 0.f, a1 = 0.f;
#pragma unroll 8
    for (int k = 0; k < N_DIM; k++) {
        float w = W1[k * H_DIM + j];
        a0 = fmaf(cs[0][k], w, a0);
        a1 = fmaf(cs[1][k], w, a1);
    }
    {
        float bb = b1[j];
        h1s[0][j] = celu1(a0 + bb);
        h1s[1][j] = celu1(a1 + bb);
    }
    __syncthreads();

    a0 = 0.f; a1 = 0.f;
#pragma unroll 8
    for (int k = 0; k < H_DIM; k++) {
        float w = W2[k * H_DIM + j];
        a0 = fmaf(h1s[0][k], w, a0);
        a1 = fmaf(h1s[1][k], w, a1);
    }
    float bb = b2[j];
    float w3 = W3[j];
    float p0v = celu1(a0 + bb) * w3;
    float p1v = celu1(a1 + bb) * w3;

#pragma unroll
    for (int off = 16; off; off >>= 1) {
        p0v += __shfl_xor_sync(0xffffffffu, p0v, off);
        p1v += __shfl_xor_sync(0xffffffffu, p1v, off);
    }
    const int wid = tid >> 5, lid = tid & 31;
    if (lid == 0) { red[0][wid] = p0v; red[1][wid] = p1v; }
    __syncthreads();
    if (tid == 0) {
        float s0 = red[0][0] + red[0][1] + red[0][2] + red[0][3];
        float s1 = red[1][0] + red[1][1] + red[1][2] + red[1][3];
        float b3v = b3[0];
        y[b0]     = s0 + b3v;
        y[b0 + 1] = s1 + b3v;
    }
}

extern "C" void kernel_launch(void* const* d_in, const int* in_sizes, int n_in,
                              void* d_out, int out_size) {
    const float* x  = (const float*)d_in[0];
    const float* W1 = (const float*)d_in[1];
    const float* b1 = (const float*)d_in[2];
    const float* W2 = (const float*)d_in[3];
    const float* b2 = (const float*)d_in[4];
    const float* W3 = (const float*)d_in[5];
    const float* b3 = (const float*)d_in[6];
    float* y = (float*)d_out;

    corr_kernel<<<B_DIM, 128>>>(x);
    mlp_kernel<<<B_DIM / 2, 128>>>(W1, b1, W2, b2, W3, b3, y);
}

// round 3
// speedup vs baseline: 1.4155x; 1.4155x over previous
#include <cuda_runtime.h>
#include <math.h>

#define B_DIM 128
#define N_DIM 1024
#define H_DIM 128

// Scratch for the correlation output (allocation-free rule: device global).
__device__ float g_c[B_DIM * N_DIM];

__device__ __forceinline__ float celu1(float v) {
    return v > 0.f ? v : expm1f(v);
}

// ---- packed fp32x2 helpers (sm_103a FFMA2) ----
__device__ __forceinline__ unsigned long long pk(float a, float b) {
    unsigned long long r;
    asm("mov.b64 %0, {%1, %2};" : "=l"(r) : "f"(a), "f"(b));
    return r;
}
__device__ __forceinline__ void ff2(unsigned long long& c,
                                    unsigned long long a, unsigned long long b) {
    asm("fma.rn.f32x2 %0, %1, %2, %0;" : "+l"(c) : "l"(a), "l"(b));
}
__device__ __forceinline__ float2 up(unsigned long long v) {
    float2 f;
    asm("mov.b64 {%0, %1}, %2;" : "=f"(f.x), "=f"(f.y) : "l"(v));
    return f;
}

// ============================================================================
// Kernel 1: circular autocorrelation per batch.
// c[b,p] = (1/N) * sum_q sum_d x[b,q,d] * x[b,(p+q)%N,d]
// Symmetry c[p] = c[(N-p)%N] -> compute p = 0..511 (+512), mirror the rest.
// One CTA per batch, 128 threads, 4 consecutive p per thread.
// Inner math in packed f32x2: accP[j] = (even-s partial, odd-s partial).
// ============================================================================
__global__ __launch_bounds__(128) void corr_kernel(const float* __restrict__ x) {
    __shared__ __align__(16) float xs[3][2 * N_DIM];

    const int b   = blockIdx.x;
    const int tid = threadIdx.x;
    const float* xb = x + (size_t)b * N_DIM * 3;

    // Load (N,3) -> SoA, duplicated 2x (kills the modulo).
    for (int i = tid; i < N_DIM * 3; i += 128) {
        float v = xb[i];
        int q = i / 3;
        int d = i - 3 * q;
        xs[d][q]         = v;
        xs[d][q + N_DIM] = v;
    }
    __syncthreads();

    const int p0 = tid * 4;   // multiple of 4 -> float4-aligned window loads

    // acc[d*4+j]: packed pair of partial sums for p = p0+j
    unsigned long long acc[12];
#pragma unroll
    for (int i = 0; i < 12; i++) acc[i] = 0ull;

    // carried window pairs per d: E0=(w0,w1), E2=(w2,w3), O1=(w1,w2)
    float2 E0[3], E2[3], O1[3];
#pragma unroll
    for (int d = 0; d < 3; d++) {
        float4 t = *(const float4*)&xs[d][p0];
        E0[d] = make_float2(t.x, t.y);
        E2[d] = make_float2(t.z, t.w);
        O1[d] = make_float2(t.y, t.z);
    }

#pragma unroll 2
    for (int q = 0; q < N_DIM; q += 8) {
#pragma unroll
        for (int d = 0; d < 3; d++) {
            const float* row = xs[d];
            float4 bA = *(const float4*)&row[q];            // broadcast
            float4 bB = *(const float4*)&row[q + 4];        // broadcast
            float4 t1 = *(const float4*)&row[q + p0 + 4];   // dense, conflict-free
            float4 t2 = *(const float4*)&row[q + p0 + 8];

            unsigned long long B0 = pk(bA.x, bA.y);
            unsigned long long B2 = pk(bA.z, bA.w);
            unsigned long long B4 = pk(bB.x, bB.y);
            unsigned long long B6 = pk(bB.z, bB.w);

            unsigned long long P0 = pk(E0[d].x, E0[d].y);
            unsigned long long P1 = pk(O1[d].x, O1[d].y);
            unsigned long long P2 = pk(E2[d].x, E2[d].y);
            unsigned long long P3 = pk(E2[d].y, t1.x);
            unsigned long long P4 = pk(t1.x, t1.y);
            unsigned long long P5 = pk(t1.y, t1.z);
            unsigned long long P6 = pk(t1.z, t1.w);
            unsigned long long P7 = pk(t1.w, t2.x);
            unsigned long long P8 = pk(t2.x, t2.y);
            unsigned long long P9 = pk(t2.y, t2.z);

            unsigned long long* a = acc + d * 4;
            ff2(a[0], B0, P0); ff2(a[0], B2, P2); ff2(a[0], B4, P4); ff2(a[0], B6, P6);
            ff2(a[1], B0, P1); ff2(a[1], B2, P3); ff2(a[1], B4, P5); ff2(a[1], B6, P7);
            ff2(a[2], B0, P2); ff2(a[2], B2, P4); ff2(a[2], B4, P6); ff2(a[2], B6, P8);
            ff2(a[3], B0, P3); ff2(a[3], B2, P5); ff2(a[3], B4, P7); ff2(a[3], B6, P9);

            E0[d] = make_float2(t2.x, t2.y);
            E2[d] = make_float2(t2.z, t2.w);
            O1[d] = make_float2(t2.y, t2.z);
        }
    }

    const float inv = 1.0f / (float)N_DIM;
    float* cb = g_c + b * N_DIM;
#pragma unroll
    for (int j = 0; j < 4; j++) {
        float2 a0 = up(acc[0 * 4 + j]);
        float2 a1 = up(acc[1 * 4 + j]);
        float2 a2 = up(acc[2 * 4 + j]);
        float v = ((a0.x + a0.y) + (a1.x + a1.y) + (a2.x + a2.y)) * inv;
        int p = p0 + j;                 // 0..511
        cb[p] = v;
        if (p > 0) cb[N_DIM - p] = v;   // mirror 513..1023
    }

    // p = 512 (self-mirror), warp 0 only.
    if (tid < 32) {
        float s = 0.f;
        for (int q = tid; q < N_DIM; q += 32) {
            s = fmaf(xs[0][q], xs[0][q + 512], s);
            s = fmaf(xs[1][q], xs[1][q + 512], s);
            s = fmaf(xs[2][q], xs[2][q + 512], s);
        }
#pragma unroll
        for (int off = 16; off; off >>= 1)
            s += __shfl_xor_sync(0xffffffffu, s, off);
        if (tid == 0) cb[512] = s * inv;
    }
}

// ============================================================================
// Kernel 2: MLP, 2 batch rows per CTA, 128 threads.
// Thread layout: jg = tid&31 -> 4 consecutive output columns (float4 W loads,
// coalesced 512B/warp); ks = tid>>5 -> K-slice. 16 LDG.128 in flight.
// ============================================================================
__device__ __forceinline__ void fma4(float4& a, float s, float4 w) {
    a.x = fmaf(s, w.x, a.x);
    a.y = fmaf(s, w.y, a.y);
    a.z = fmaf(s, w.z, a.z);
    a.w = fmaf(s, w.w, a.w);
}

__global__ __launch_bounds__(128) void mlp_kernel(
    const float* __restrict__ W1, const float* __restrict__ b1,
    const float* __restrict__ W2, const float* __restrict__ b2,
    const float* __restrict__ W3, const float* __restrict__ b3,
    float* __restrict__ y)
{
    __shared__ __align__(16) float cs[2][N_DIM];        // 8KB
    __shared__ __align__(16) float red[4][2][H_DIM];    // 4KB partials
    __shared__ float h1s[2][H_DIM];
    __shared__ float rsum[2][4];

    const int b0  = blockIdx.x * 2;
    const int tid = threadIdx.x;
    const int jg  = tid & 31;      // column group: cols 4*jg .. 4*jg+3
    const int ks  = tid >> 5;      // K-slice id (warp id)

    // Stage the two c rows (vectorized, coalesced).
    {
        const float4* src = (const float4*)(g_c + (size_t)b0 * N_DIM);
        float4* dst = (float4*)cs;
        for (int i = tid; i < 2 * N_DIM / 4; i += 128) dst[i] = src[i];
    }
    __syncthreads();

    // ---------- Layer 1: 1024 -> 128 ----------
    float4 acc0 = make_float4(0.f, 0.f, 0.f, 0.f);
    float4 acc1 = make_float4(0.f, 0.f, 0.f, 0.f);
    {
        const int k0 = ks * 256;
#pragma unroll 4
        for (int kk = 0; kk < 256; kk += 4) {
            const int k = k0 + kk;
            float4 c0 = *(const float4*)&cs[0][k];   // broadcast within warp
            float4 c1 = *(const float4*)&cs[1][k];
            float4 w0 = *(const float4*)&W1[(size_t)(k + 0) * H_DIM + 4 * jg];
            float4 w1 = *(const float4*)&W1[(size_t)(k + 1) * H_DIM + 4 * jg];
            float4 w2 = *(const float4*)&W1[(size_t)(k + 2) * H_DIM + 4 * jg];
            float4 w3 = *(const float4*)&W1[(size_t)(k + 3) * H_DIM + 4 * jg];
            fma4(acc0, c0.x, w0); fma4(acc1, c1.x, w0);
            fma4(acc0, c0.y, w1); fma4(acc1, c1.y, w1);
            fma4(acc0, c0.z, w2); fma4(acc1, c1.z, w2);
            fma4(acc0, c0.w, w3); fma4(acc1, c1.w, w3);
        }
    }
    *(float4*)&red[ks][0][4 * jg] = acc0;
    *(float4*)&red[ks][1][4 * jg] = acc1;
    __syncthreads();

    // reduce across the 4 K-slices; thread t owns column t
#pragma unroll
    for (int r = 0; r < 2; r++) {
        float s = red[0][r][tid] + red[1][r][tid] + red[2][r][tid] + red[3][r][tid];
        h1s[r][tid] = celu1(s + b1[tid]);
    }
    __syncthreads();

    // ---------- Layer 2: 128 -> 128 ----------
    acc0 = make_float4(0.f, 0.f, 0.f, 0.f);
    acc1 = make_float4(0.f, 0.f, 0.f, 0.f);
    {
        const int k0 = ks * 32;
#pragma unroll 8
        for (int kk = 0; kk < 32; kk++) {
            const int k = k0 + kk;
            float4 w = *(const float4*)&W2[(size_t)k * H_DIM + 4 * jg];
            fma4(acc0, h1s[0][k], w);
            fma4(acc1, h1s[1][k], w);
        }
    }
    __syncthreads();   // h1s consumed; red free to reuse
    *(float4*)&red[ks][0][4 * jg] = acc0;
    *(float4*)&red[ks][1][4 * jg] = acc1;
    __syncthreads();

    // ---------- Layer 3 + reduction ----------
    float w3v = W3[tid];
    float v0, v1;
    {
        float s0 = red[0][0][tid] + red[1][0][tid] + red[2][0][tid] + red[3][0][tid];
        float s1 = red[0][1][tid] + red[1][1][tid] + red[2][1][tid] + red[3][1][tid];
        v0 = celu1(s0 + b2[tid]) * w3v;
        v1 = celu1(s1 + b2[tid]) * w3v;
    }
#pragma unroll
    for (int off = 16; off; off >>= 1) {
        v0 += __shfl_xor_sync(0xffffffffu, v0, off);
        v1 += __shfl_xor_sync(0xffffffffu, v1, off);
    }
    const int lid = tid & 31;
    if (lid == 0) { rsum[0][ks] = v0; rsum[1][ks] = v1; }
    __syncthreads();
    if (tid == 0) {
        float b3v = b3[0];
        y[b0]     = rsum[0][0] + rsum[0][1] + rsum[0][2] + rsum[0][3] + b3v;
        y[b0 + 1] = rsum[1][0] + rsum[1][1] + rsum[1][2] + rsum[1][3] + b3v;
    }
}

extern "C" void kernel_launch(void* const* d_in, const int* in_sizes, int n_in,
                              void* d_out, int out_size) {
    const float* x  = (const float*)d_in[0];
    const float* W1 = (const float*)d_in[1];
    const float* b1 = (const float*)d_in[2];
    const float* W2 = (const float*)d_in[3];
    const float* b2 = (const float*)d_in[4];
    const float* W3 = (const float*)d_in[5];
    const float* b3 = (const float*)d_in[6];
    float* y = (float*)d_out;

    corr_kernel<<<B_DIM, 128>>>(x);
    mlp_kernel<<<B_DIM / 2, 128>>>(W1, b1, W2, b2, W3, b3, y);
}

// round 4
// speedup vs baseline: 1.7445x; 1.2325x over previous
#include <cuda_runtime.h>
#include <math.h>

#define B_DIM 128
#define N_DIM 1024
#define H_DIM 128
#define SK    128          // split-K factor for layer 1
#define KC    (N_DIM / SK) // 8: K-chunk per CTA

// Scratch (allocation-free rule: device globals).
__device__ float g_c[B_DIM * N_DIM];                    // 512 KB correlation output
__device__ float g_part[SK * B_DIM * H_DIM];            // 8 MB layer-1 partials

__device__ __forceinline__ float celu1(float v) {
    return v > 0.f ? v : expm1f(v);
}

// ---- packed fp32x2 helpers (sm_103a FFMA2) ----
__device__ __forceinline__ unsigned long long pk(float a, float b) {
    unsigned long long r;
    asm("mov.b64 %0, {%1, %2};" : "=l"(r) : "f"(a), "f"(b));
    return r;
}
__device__ __forceinline__ void ff2(unsigned long long& c,
                                    unsigned long long a, unsigned long long b) {
    asm("fma.rn.f32x2 %0, %1, %2, %0;" : "+l"(c) : "l"(a), "l"(b));
}
__device__ __forceinline__ float2 up(unsigned long long v) {
    float2 f;
    asm("mov.b64 {%0, %1}, %2;" : "=f"(f.x), "=f"(f.y) : "l"(v));
    return f;
}

// ============================================================================
// Kernel 1: circular autocorrelation per batch (unchanged from R3).
// c[b,p] = (1/N) * sum_q sum_d x[b,q,d] * x[b,(p+q)%N,d];   c[p] = c[(N-p)%N]
// ============================================================================
__global__ __launch_bounds__(128) void corr_kernel(const float* __restrict__ x) {
    __shared__ __align__(16) float xs[3][2 * N_DIM];

    const int b   = blockIdx.x;
    const int tid = threadIdx.x;
    const float* xb = x + (size_t)b * N_DIM * 3;

    for (int i = tid; i < N_DIM * 3; i += 128) {
        float v = xb[i];
        int q = i / 3;
        int d = i - 3 * q;
        xs[d][q]         = v;
        xs[d][q + N_DIM] = v;
    }
    __syncthreads();

    const int p0 = tid * 4;

    unsigned long long acc[12];
#pragma unroll
    for (int i = 0; i < 12; i++) acc[i] = 0ull;

    float2 E0[3], E2[3], O1[3];
#pragma unroll
    for (int d = 0; d < 3; d++) {
        float4 t = *(const float4*)&xs[d][p0];
        E0[d] = make_float2(t.x, t.y);
        E2[d] = make_float2(t.z, t.w);
        O1[d] = make_float2(t.y, t.z);
    }

#pragma unroll 2
    for (int q = 0; q < N_DIM; q += 8) {
#pragma unroll
        for (int d = 0; d < 3; d++) {
            const float* row = xs[d];
            float4 bA = *(const float4*)&row[q];
            float4 bB = *(const float4*)&row[q + 4];
            float4 t1 = *(const float4*)&row[q + p0 + 4];
            float4 t2 = *(const float4*)&row[q + p0 + 8];

            unsigned long long B0 = pk(bA.x, bA.y);
            unsigned long long B2 = pk(bA.z, bA.w);
            unsigned long long B4 = pk(bB.x, bB.y);
            unsigned long long B6 = pk(bB.z, bB.w);

            unsigned long long P0 = pk(E0[d].x, E0[d].y);
            unsigned long long P1 = pk(O1[d].x, O1[d].y);
            unsigned long long P2 = pk(E2[d].x, E2[d].y);
            unsigned long long P3 = pk(E2[d].y, t1.x);
            unsigned long long P4 = pk(t1.x, t1.y);
            unsigned long long P5 = pk(t1.y, t1.z);
            unsigned long long P6 = pk(t1.z, t1.w);
            unsigned long long P7 = pk(t1.w, t2.x);
            unsigned long long P8 = pk(t2.x, t2.y);
            unsigned long long P9 = pk(t2.y, t2.z);

            unsigned long long* a = acc + d * 4;
            ff2(a[0], B0, P0); ff2(a[0], B2, P2); ff2(a[0], B4, P4); ff2(a[0], B6, P6);
            ff2(a[1], B0, P1); ff2(a[1], B2, P3); ff2(a[1], B4, P5); ff2(a[1], B6, P7);
            ff2(a[2], B0, P2); ff2(a[2], B2, P4); ff2(a[2], B4, P6); ff2(a[2], B6, P8);
            ff2(a[3], B0, P3); ff2(a[3], B2, P5); ff2(a[3], B4, P7); ff2(a[3], B6, P9);

            E0[d] = make_float2(t2.x, t2.y);
            E2[d] = make_float2(t2.z, t2.w);
            O1[d] = make_float2(t2.y, t2.z);
        }
    }

    const float inv = 1.0f / (float)N_DIM;
    float* cb = g_c + b * N_DIM;
#pragma unroll
    for (int j = 0; j < 4; j++) {
        float2 a0 = up(acc[0 * 4 + j]);
        float2 a1 = up(acc[1 * 4 + j]);
        float2 a2 = up(acc[2 * 4 + j]);
        float v = ((a0.x + a0.y) + (a1.x + a1.y) + (a2.x + a2.y)) * inv;
        int p = p0 + j;
        cb[p] = v;
        if (p > 0) cb[N_DIM - p] = v;
    }

    if (tid < 32) {
        float s = 0.f;
        for (int q = tid; q < N_DIM; q += 32) {
            s = fmaf(xs[0][q], xs[0][q + 512], s);
            s = fmaf(xs[1][q], xs[1][q + 512], s);
            s = fmaf(xs[2][q], xs[2][q + 512], s);
        }
#pragma unroll
        for (int off = 16; off; off >>= 1)
            s += __shfl_xor_sync(0xffffffffu, s, off);
        if (tid == 0) cb[512] = s * inv;
    }
}

// ============================================================================
// Kernel 2: layer 1 as split-K GEMM.  C[128,1024] @ W1[1024,128].
// Grid = SK CTAs; CTA sk handles K-chunk [sk*KC, sk*KC+KC).
// SMEM-staged operands, 8x8 register tile per thread (256 threads = 16x16).
// Writes fp32 partial [128,128] to g_part[sk].
// ============================================================================
__global__ __launch_bounds__(256) void l1_kernel(const float* __restrict__ W1) {
    __shared__ __align__(16) float ct[KC][B_DIM];   // c^T chunk: [kk][m]
    __shared__ __align__(16) float wt[KC][H_DIM];   // W1 chunk:  [kk][n]

    const int sk = blockIdx.x;
    const int k0 = sk * KC;
    const int t  = threadIdx.x;

    // Stage c chunk transposed: c[m][k0+kk] -> ct[kk][m]
    {
        int m = t >> 1, h = t & 1;
        float4 v = *(const float4*)&g_c[(size_t)m * N_DIM + k0 + 4 * h];
        ct[4 * h + 0][m] = v.x;
        ct[4 * h + 1][m] = v.y;
        ct[4 * h + 2][m] = v.z;
        ct[4 * h + 3][m] = v.w;
    }
    // Stage W1 chunk: 8 rows x 512B, straight copy
    {
        int kk = t >> 5, q = t & 31;
        *(float4*)&wt[kk][4 * q] =
            *(const float4*)&W1[(size_t)(k0 + kk) * H_DIM + 4 * q];
    }
    __syncthreads();

    const int m0 = (t >> 4) * 8;   // 8 batch rows
    const int n0 = (t & 15) * 8;   // 8 output cols

    float4 acc[8][2];
#pragma unroll
    for (int i = 0; i < 8; i++) {
        acc[i][0] = make_float4(0.f, 0.f, 0.f, 0.f);
        acc[i][1] = make_float4(0.f, 0.f, 0.f, 0.f);
    }

#pragma unroll
    for (int kk = 0; kk < KC; kk++) {
        float4 aA = *(const float4*)&ct[kk][m0];
        float4 aB = *(const float4*)&ct[kk][m0 + 4];
        float4 b0 = *(const float4*)&wt[kk][n0];
        float4 b1 = *(const float4*)&wt[kk][n0 + 4];
        float a[8] = {aA.x, aA.y, aA.z, aA.w, aB.x, aB.y, aB.z, aB.w};
#pragma unroll
        for (int i = 0; i < 8; i++) {
            acc[i][0].x = fmaf(a[i], b0.x, acc[i][0].x);
            acc[i][0].y = fmaf(a[i], b0.y, acc[i][0].y);
            acc[i][0].z = fmaf(a[i], b0.z, acc[i][0].z);
            acc[i][0].w = fmaf(a[i], b0.w, acc[i][0].w);
            acc[i][1].x = fmaf(a[i], b1.x, acc[i][1].x);
            acc[i][1].y = fmaf(a[i], b1.y, acc[i][1].y);
            acc[i][1].z = fmaf(a[i], b1.z, acc[i][1].z);
            acc[i][1].w = fmaf(a[i], b1.w, acc[i][1].w);
        }
    }

    float* dst = g_part + (size_t)sk * B_DIM * H_DIM;
#pragma unroll
    for (int i = 0; i < 8; i++) {
        *(float4*)&dst[(size_t)(m0 + i) * H_DIM + n0]     = acc[i][0];
        *(float4*)&dst[(size_t)(m0 + i) * H_DIM + n0 + 4] = acc[i][1];
    }
}

// ============================================================================
// Kernel 3: per-batch tail. Reduce split-K partials -> +b1, celu -> layer 2
// -> +b2, celu -> layer 3 -> y.  Grid = 128 (1 CTA/batch), 256 threads,
// 2-way K-split per phase; every reduction in fixed order (deterministic).
// ============================================================================
__global__ __launch_bounds__(256) void mlp_tail_kernel(
    const float* __restrict__ b1, const float* __restrict__ W2,
    const float* __restrict__ b2, const float* __restrict__ W3,
    const float* __restrict__ b3, float* __restrict__ y)
{
    __shared__ float h1s[H_DIM];
    __shared__ float red[256];
    __shared__ float rsum[4];

    const int m = blockIdx.x;
    const int t = threadIdx.x;
    const int j    = t & 127;
    const int half = t >> 7;

    // ---- phase 1: reduce 128 split-K partials (64 per half) ----
    float s = 0.f;
    {
        const float* base = g_part + (size_t)half * 64 * (B_DIM * H_DIM)
                                   + (size_t)m * H_DIM + j;
#pragma unroll 16
        for (int sk = 0; sk < 64; sk++)
            s += base[(size_t)sk * (B_DIM * H_DIM)];
    }
    red[t] = s;
    __syncthreads();
    if (half == 0)
        h1s[j] = celu1(red[j] + red[j + 128] + b1[j]);
    __syncthreads();

    // ---- phase 2: layer 2 (128 -> 128), 2-way K-split ----
    float a = 0.f;
    {
        const float* w = W2 + (size_t)half * 64 * H_DIM + j;
        const float* h = h1s + half * 64;
#pragma unroll 16
        for (int k = 0; k < 64; k++)
            a = fmaf(h[k], w[(size_t)k * H_DIM], a);
    }
    __syncthreads();           // h1s fully consumed before red reuse is safe
    red[t] = a;
    __syncthreads();

    // ---- phase 3: celu, layer 3, reduce ----
    float v = 0.f;
    if (half == 0) {
        float h2 = celu1(red[j] + red[j + 128] + b2[j]);
        v = h2 * W3[j];
#pragma unroll
        for (int off = 16; off; off >>= 1)
            v += __shfl_xor_sync(0xffffffffu, v, off);
        if ((j & 31) == 0) rsum[j >> 5] = v;
    }
    __syncthreads();
    if (t == 0)
        y[m] = rsum[0] + rsum[1] + rsum[2] + rsum[3] + b3[0];
}

extern "C" void kernel_launch(void* const* d_in, const int* in_sizes, int n_in,
                              void* d_out, int out_size) {
    const float* x  = (const float*)d_in[0];
    const float* W1 = (const float*)d_in[1];
    const float* b1 = (const float*)d_in[2];
    const float* W2 = (const float*)d_in[3];
    const float* b2 = (const float*)d_in[4];
    const float* W3 = (const float*)d_in[5];
    const float* b3 = (const float*)d_in[6];
    float* y = (float*)d_out;

    corr_kernel<<<B_DIM, 128>>>(x);
    l1_kernel<<<SK, 256>>>(W1);
    mlp_tail_kernel<<<B_DIM, 256>>>(b1, W2, b2, W3, b3, y);
}